// round 13
// baseline (speedup 1.0000x reference)
#include <cuda_runtime.h>
#include <cuda_bf16.h>
#include <cstdint>
#include <math.h>

// Problem dims (fixed)
#define B_   4
#define L_   2048
#define D_   2048
#define R_   (B_*L_)        // 8192 rows
#define WN_  4
#define WELEM (D_*D_)       // 4194304
#define NCHUNK 64
#define CHUNK  32           // L_/NCHUNK

// ---------------- scratch (static device allocations; no cudaMalloc) ------
__device__ __align__(16) __nv_bfloat16 g_WQ[WN_*WELEM]; // ternary weights (32MB)
__device__ __align__(16) __nv_bfloat16 g_XQ[R_*D_];     // quantized acts  (32MB)
__device__ float g_GOUT[(size_t)R_*3*D_];        // raw int sums i|f|g      (192MB)
__device__ float g_SA[R_*D_];                    // h*sigmoid(h)            (64MB)
__device__ float g_cF[B_*NCHUNK*D_];
__device__ float g_cH[B_*NCHUNK*D_];
__device__ float g_carry[B_*NCHUNK*D_];
__device__ float g_xs[R_];                       // per-row act dequant scale
__device__ float g_os[R_];                       // per-row o dequant scale
__device__ float g_wpart[WN_*256];
__device__ float g_wmean[WN_];                   // clip(mean|W|,1e-5) == 1/ws

// ---------------- helpers ----------------
__device__ __forceinline__ float sigmoidf_(float x) { return 1.0f / (1.0f + expf(-x)); }
__device__ __forceinline__ float rsqrt_acc(float v) {
    float r = rsqrtf(v);
    r = r * (1.5f - 0.5f * v * r * r);
    return r;
}
__device__ __forceinline__ uint32_t smem_u32(const void* p) {
    uint32_t a;
    asm("{ .reg .u64 t; cvta.to.shared.u64 t, %1; cvt.u32.u64 %0, t; }" : "=r"(a) : "l"(p));
    return a;
}
// Deterministic block reductions (256 threads): shuffle within warp, smem
// broadcast of 8 warp partials, identical final value in every thread.
__device__ __forceinline__ float blk_sum(float v, float* red8, int tid) {
    #pragma unroll
    for (int o = 16; o > 0; o >>= 1) v += __shfl_xor_sync(0xFFFFFFFFu, v, o);
    if ((tid & 31) == 0) red8[tid >> 5] = v;
    __syncthreads();
    float s = 0.f;
    #pragma unroll
    for (int w = 0; w < 8; w++) s += red8[w];
    __syncthreads();
    return s;
}
__device__ __forceinline__ float blk_max(float v, float* red8, int tid) {
    #pragma unroll
    for (int o = 16; o > 0; o >>= 1) v = fmaxf(v, __shfl_xor_sync(0xFFFFFFFFu, v, o));
    if ((tid & 31) == 0) red8[tid >> 5] = v;
    __syncthreads();
    float s = red8[0];
    #pragma unroll
    for (int w = 1; w < 8; w++) s = fmaxf(s, red8[w]);
    __syncthreads();
    return s;
}

// ---------------- weight abs-mean: deterministic two-stage reduction -------
__global__ void k_wabs_partial(const float* __restrict__ W0, const float* __restrict__ W1,
                               const float* __restrict__ W2, const float* __restrict__ W3) {
    const float* W = (blockIdx.y == 0) ? W0 : (blockIdx.y == 1) ? W1 : (blockIdx.y == 2) ? W2 : W3;
    int tid = threadIdx.x;
    size_t base = (size_t)blockIdx.x * 16384 + tid;
    float s = 0.f;
    #pragma unroll 8
    for (int j = 0; j < 64; j++) s += fabsf(W[base + (size_t)j * 256]);
    __shared__ float red8[8];
    s = blk_sum(s, red8, tid);
    if (tid == 0) g_wpart[blockIdx.y * 256 + blockIdx.x] = s;
}

__global__ void k_wfinal() {
    int w = blockIdx.x, tid = threadIdx.x;
    __shared__ float red8[8];
    float s = blk_sum(g_wpart[w * 256 + tid], red8, tid);
    if (tid == 0) {
        float m = s / (float)WELEM;
        g_wmean[w] = fmaxf(m, 1e-5f);
    }
}

// ---------------- ternary weight quantization -> bf16 ----------------------
__global__ void k_wquant(const float* __restrict__ W0, const float* __restrict__ W1,
                         const float* __restrict__ W2, const float* __restrict__ W3) {
    int i = blockIdx.x * blockDim.x + threadIdx.x;     // over WN_*WELEM/4
    int w = i >> 20;
    const float* W = (w == 0) ? W0 : (w == 1) ? W1 : (w == 2) ? W2 : W3;
    float4 v = ((const float4*)W)[i & 0xFFFFF];
    float ws = 1.0f / g_wmean[w];
    size_t o = (size_t)i * 4;
    g_WQ[o + 0] = __float2bfloat16(fminf(fmaxf(rintf(v.x * ws), -1.f), 1.f));
    g_WQ[o + 1] = __float2bfloat16(fminf(fmaxf(rintf(v.y * ws), -1.f), 1.f));
    g_WQ[o + 2] = __float2bfloat16(fminf(fmaxf(rintf(v.z * ws), -1.f), 1.f));
    g_WQ[o + 3] = __float2bfloat16(fminf(fmaxf(rintf(v.w * ws), -1.f), 1.f));
}

// ---------------- activation quantization (RMSNorm -> int8 grid, bf16) -----
__global__ void k_actquant(const float* __restrict__ X) {
    int row = blockIdx.x, tid = threadIdx.x;
    const float* xr = X + (size_t)row * D_;
    __shared__ float red8[8];
    float v[8]; float ss = 0.f;
    #pragma unroll
    for (int j = 0; j < 8; j++) { v[j] = xr[tid + j * 256]; ss += v[j] * v[j]; }
    float tot = blk_sum(ss, red8, tid);
    float rms = rsqrt_acc(tot / (float)D_ + 1e-5f);
    float ma = 0.f;
    #pragma unroll
    for (int j = 0; j < 8; j++) { v[j] *= rms; ma = fmaxf(ma, fabsf(v[j])); }
    float mx = fmaxf(blk_max(ma, red8, tid), 1e-5f);
    float s = 127.f / mx;
    #pragma unroll
    for (int j = 0; j < 8; j++) {
        float q = fminf(fmaxf(rintf(v[j] * s), -128.f), 127.f);
        g_XQ[(size_t)row * D_ + tid + j * 256] = __float2bfloat16(q);
    }
    if (tid == 0) g_xs[row] = mx / 127.f;
}

// ---------------- bf16 HMMA GEMM: warp tile 64x64, CTA 128x256 -------------
// C[m,n] = sum_k A[m,k]*B[n,k]. 256 thr = 8 warps (2m x 4n), warp 64x64.
// Per warp-k16: 8 LDSM + 32 HMMA (4:1). BK=64, 3-stage cp.async, 1 sync.
#define STAGES 3
#define ROWB   144                      // padded row stride (bytes): 128 + 16
#define ATILEB (128*ROWB)               // 18432
#define BTILEB (256*ROWB)               // 36864
#define STGB   (ATILEB+BTILEB)          // 55296
#define GSMEM  (STAGES*STGB)            // 165888

__device__ __forceinline__ void cp16(uint32_t dst, const void* src) {
    asm volatile("cp.async.cg.shared.global [%0], [%1], 16;" :: "r"(dst), "l"(src));
}
#define LDSM4(r0, r1, r2, r3, addr) \
    asm volatile("ldmatrix.sync.aligned.m8n8.x4.shared.b16 {%0,%1,%2,%3}, [%4];" \
        : "=r"(r0), "=r"(r1), "=r"(r2), "=r"(r3) : "r"(addr))

__global__ void __launch_bounds__(256, 1) k_gemm_bf16(
    const __nv_bfloat16* __restrict__ A, const __nv_bfloat16* __restrict__ Bm,
    float* __restrict__ C, int N,
    const float* __restrict__ rowscale, const float* __restrict__ wscale) {

    extern __shared__ char sm8[];
    uint32_t sb = smem_u32(sm8);
    const int K = D_;
    int tid = threadIdx.x, lane = tid & 31, warp = tid >> 5;
    int wm = (warp & 1) * 64, wn = (warp >> 1) * 64;
    int g = lane >> 2, t4 = lane & 3;
    int bm = blockIdx.y * 128, bn = blockIdx.x * 256;

    const __nv_bfloat16* Ab = A + (size_t)bm * K;
    const __nv_bfloat16* Bb = Bm + (size_t)bn * K;

    float acc[4][8][4];
    #pragma unroll
    for (int a = 0; a < 4; a++)
        #pragma unroll
        for (int b = 0; b < 8; b++)
            #pragma unroll
            for (int c = 0; c < 4; c++) acc[a][b][c] = 0.f;

    // ldmatrix per-lane address offsets (within a stage; kk*32 added later).
    uint32_t aoff[4], boff[4];
    {
        int l = lane;
        int rlo = (l & 7) + ((l >> 3) & 1) * 8;      // +8 for tiles 1,3
        int khalf = (l >> 4) * 16;                   // +16B for tiles 2,3
        #pragma unroll
        for (int mi = 0; mi < 4; mi++)
            aoff[mi] = (uint32_t)((wm + mi * 16 + rlo) * ROWB + khalf);
        int nrow = (l & 7) + (l >> 4) * 8;           // +8 rows for tiles 2,3
        int bk = ((l >> 3) & 1) * 16;                // +16B for tiles 1,3
        #pragma unroll
        for (int p = 0; p < 4; p++)
            boff[p] = (uint32_t)((wn + p * 16 + nrow) * ROWB + bk);
    }

    // copy mapping: per stage 3072 chunks of 16B (1024 A + 2048 B), 12/thread.
    // A chunk c: row = c>>3, kc = c&7.  B chunk c-1024 likewise.

    #pragma unroll
    for (int s = 0; s < STAGES - 1; s++) {
        #pragma unroll
        for (int i = 0; i < 12; i++) {
            int id = tid + i * 256;
            int isB = (id >= 1024);
            int c = isB ? (id - 1024) : id;
            int row = c >> 3, kc = c & 7;
            const __nv_bfloat16* src = (isB ? Bb : Ab) + (size_t)row * K + s * 64 + kc * 8;
            cp16(sb + s * STGB + (isB ? ATILEB : 0) + row * ROWB + kc * 16, src);
        }
        asm volatile("cp.async.commit_group;");
    }

    for (int kt = 0; kt < 32; kt++) {                 // 32 K-tiles of 64
        asm volatile("cp.async.wait_group %0;" :: "n"(STAGES - 2));
        __syncthreads();

        int pf = kt + STAGES - 1;
        if (pf < 32) {
            int s = pf % STAGES;
            #pragma unroll
            for (int i = 0; i < 12; i++) {
                int id = tid + i * 256;
                int isB = (id >= 1024);
                int c = isB ? (id - 1024) : id;
                int row = c >> 3, kc = c & 7;
                const __nv_bfloat16* src = (isB ? Bb : Ab) + (size_t)row * K + pf * 64 + kc * 8;
                cp16(sb + s * STGB + (isB ? ATILEB : 0) + row * ROWB + kc * 16, src);
            }
            asm volatile("cp.async.commit_group;");
        } else {
            asm volatile("cp.async.commit_group;");   // keep group count in sync
        }

        uint32_t aB = sb + (kt % STAGES) * STGB;
        uint32_t bB = aB + ATILEB;
        #pragma unroll
        for (int kk = 0; kk < 4; kk++) {              // four k16 slices, 32B each
            uint32_t af[4][4], bf[8][2];
            #pragma unroll
            for (int mi = 0; mi < 4; mi++)
                LDSM4(af[mi][0], af[mi][1], af[mi][2], af[mi][3],
                      aB + aoff[mi] + kk * 32);
            #pragma unroll
            for (int p = 0; p < 4; p++)
                LDSM4(bf[2 * p][0], bf[2 * p][1], bf[2 * p + 1][0], bf[2 * p + 1][1],
                      bB + boff[p] + kk * 32);
            #pragma unroll
            for (int mi = 0; mi < 4; mi++)
                #pragma unroll
                for (int ni = 0; ni < 8; ni++) {
                    asm volatile(
                        "mma.sync.aligned.m16n8k16.row.col.f32.bf16.bf16.f32 "
                        "{%0,%1,%2,%3}, {%4,%5,%6,%7}, {%8,%9}, {%0,%1,%2,%3};\n"
                        : "+f"(acc[mi][ni][0]), "+f"(acc[mi][ni][1]),
                          "+f"(acc[mi][ni][2]), "+f"(acc[mi][ni][3])
                        : "r"(af[mi][0]), "r"(af[mi][1]), "r"(af[mi][2]), "r"(af[mi][3]),
                          "r"(bf[ni][0]), "r"(bf[ni][1]));
                }
        }
    }

    float wsc = rowscale ? (*wscale) : 1.f;
    #pragma unroll
    for (int mi = 0; mi < 4; mi++) {
        int r0 = bm + wm + mi * 16 + g;
        int r1 = r0 + 8;
        float s0 = rowscale ? rowscale[r0] * wsc : 1.f;
        float s1 = rowscale ? rowscale[r1] * wsc : 1.f;
        #pragma unroll
        for (int ni = 0; ni < 8; ni++) {
            int col = bn + wn + ni * 8 + t4 * 2;
            float2 v0, v1;
            v0.x = acc[mi][ni][0] * s0;
            v0.y = acc[mi][ni][1] * s0;
            v1.x = acc[mi][ni][2] * s1;
            v1.y = acc[mi][ni][3] * s1;
            *(float2*)&C[(size_t)r0 * N + col] = v0;
            *(float2*)&C[(size_t)r1 * N + col] = v1;
        }
    }
}

// ---------------- HGRN scan (3-pass chunked, i/f recomputed from GOUT) -----
__global__ void k_scan1() {
    int idx = blockIdx.x * 256 + threadIdx.x;   // B_*NCHUNK*D_ = 524288
    int d = idx & 2047, c = (idx >> 11) & (NCHUNK - 1), b = idx >> 17;
    int row0 = b * L_ + c * CHUNK;
    float w0 = g_wmean[0], w1 = g_wmean[1];
    float F = 1.f, H = 0.f;
    for (int t = 0; t < CHUNK; t++) {
        int row = row0 + t;
        float sx = g_xs[row];
        float iv = g_GOUT[(size_t)row * 6144 + d       ] * (sx * w0);
        float fv = g_GOUT[(size_t)row * 6144 + 2048 + d] * (sx * w1);
        float f = sigmoidf_(fv);
        float i = iv * sigmoidf_(iv) * (1.f - f);
        H = f * H + i;
        F *= f;
    }
    int o = (b * NCHUNK + c) * D_ + d;
    g_cF[o] = F; g_cH[o] = H;
}

__global__ void k_scan2() {
    int idx = blockIdx.x * 256 + threadIdx.x;   // B_*D_ = 8192
    int d = idx & 2047, b = idx >> 11;
    float carry = 0.f;
    for (int c = 0; c < NCHUNK; c++) {
        int o = (b * NCHUNK + c) * D_ + d;
        g_carry[o] = carry;
        carry = g_cF[o] * carry + g_cH[o];
    }
}

__global__ void k_scan3() {
    int idx = blockIdx.x * 256 + threadIdx.x;   // B_*NCHUNK*D_
    int d = idx & 2047, c = (idx >> 11) & (NCHUNK - 1), b = idx >> 17;
    int row0 = b * L_ + c * CHUNK;
    float w0 = g_wmean[0], w1 = g_wmean[1];
    float h = g_carry[(b * NCHUNK + c) * D_ + d];
    for (int t = 0; t < CHUNK; t++) {
        int row = row0 + t;
        float sx = g_xs[row];
        float iv = g_GOUT[(size_t)row * 6144 + d       ] * (sx * w0);
        float fv = g_GOUT[(size_t)row * 6144 + 2048 + d] * (sx * w1);
        float f = sigmoidf_(fv);
        float i = iv * sigmoidf_(iv) * (1.f - f);
        h = f * h + i;
        g_SA[(size_t)row * D_ + d] = h * sigmoidf_(h);
    }
}

// ---------------- o = rmsnorm(g)*w*(h*sig(h)), then re-quantize o ----------
__global__ void k_og(const float* __restrict__ gnw) {
    int row = blockIdx.x, tid = threadIdx.x;
    __shared__ float red8[8];
    float sg = g_xs[row] * g_wmean[2];
    float gv[8]; float ss = 0.f;
    #pragma unroll
    for (int j = 0; j < 8; j++) {
        gv[j] = g_GOUT[(size_t)row * 6144 + 4096 + tid + j * 256] * sg;
        ss += gv[j] * gv[j];
    }
    float tot = blk_sum(ss, red8, tid);
    float rg = rsqrt_acc(tot / (float)D_ + 1e-5f);

    float ov[8]; ss = 0.f;
    #pragma unroll
    for (int j = 0; j < 8; j++) {
        float hs = g_SA[(size_t)row * D_ + tid + j * 256];
        ov[j] = gv[j] * rg * gnw[tid + j * 256] * hs;
        ss += ov[j] * ov[j];
    }
    float tot2 = blk_sum(ss, red8, tid);
    float ro = rsqrt_acc(tot2 / (float)D_ + 1e-5f);

    float ma = 0.f;
    #pragma unroll
    for (int j = 0; j < 8; j++) { ov[j] *= ro; ma = fmaxf(ma, fabsf(ov[j])); }
    float mx = fmaxf(blk_max(ma, red8, tid), 1e-5f);
    float s = 127.f / mx;
    #pragma unroll
    for (int j = 0; j < 8; j++) {
        float q = fminf(fmaxf(rintf(ov[j] * s), -128.f), 127.f);
        g_XQ[(size_t)row * D_ + tid + j * 256] = __float2bfloat16(q);
    }
    if (tid == 0) g_os[row] = mx / 127.f;
}

// ---------------- launch ---------------------------------------------------
extern "C" void kernel_launch(void* const* d_in, const int* in_sizes, int n_in,
                              void* d_out, int out_size) {
    const float* X   = (const float*)d_in[0];
    const float* Wi  = (const float*)d_in[1];
    const float* Wf  = (const float*)d_in[2];
    const float* Wg  = (const float*)d_in[3];
    const float* Wo  = (const float*)d_in[4];
    const float* gnw = (const float*)d_in[5];
    float* out = (float*)d_out;

    void *pWQ = nullptr, *pXQ = nullptr, *pGOUT = nullptr, *pOS = nullptr, *pWM = nullptr;
    cudaGetSymbolAddress(&pWQ, g_WQ);
    cudaGetSymbolAddress(&pXQ, g_XQ);
    cudaGetSymbolAddress(&pGOUT, g_GOUT);
    cudaGetSymbolAddress(&pOS, g_os);
    cudaGetSymbolAddress(&pWM, g_wmean);

    cudaFuncSetAttribute(k_gemm_bf16, cudaFuncAttributeMaxDynamicSharedMemorySize, GSMEM);

    // 1. weight scales (deterministic)
    k_wabs_partial<<<dim3(256, 4), 256>>>(Wi, Wf, Wg, Wo);
    k_wfinal<<<4, 256>>>();
    // 2. quantize weights (ternary bf16)
    k_wquant<<<16384, 256>>>(Wi, Wf, Wg, Wo);
    // 3. quantize activations (bf16 int grid)
    k_actquant<<<R_, 256>>>(X);
    // 4. fused HMMA GEMM for i|f|g raw integer sums: [8192 x 6144 x 2048]
    k_gemm_bf16<<<dim3(6144 / 256, R_ / 128), 256, GSMEM>>>(
        (const __nv_bfloat16*)pXQ, (const __nv_bfloat16*)pWQ, (float*)pGOUT,
        3 * D_, nullptr, nullptr);
    // 5. HGRN scan (64 chunks of 32; i/f recomputed from GOUT, no staging)
    k_scan1<<<(B_ * NCHUNK * D_) / 256, 256>>>();
    k_scan2<<<(B_ * D_) / 256, 256>>>();
    k_scan3<<<(B_ * NCHUNK * D_) / 256, 256>>>();
    // 6. output gate + o quantization
    k_og<<<R_, 256>>>(gnw);
    // 7. final HMMA GEMM with dequant epilogue -> d_out
    k_gemm_bf16<<<dim3(D_ / 256, R_ / 128), 256, GSMEM>>>(
        (const __nv_bfloat16*)pXQ, (const __nv_bfloat16*)pWQ + (size_t)3 * WELEM, out,
        D_, (const float*)pOS, (const float*)pWM + 3);
}

// round 14
// speedup vs baseline: 1.1428x; 1.1428x over previous
#include <cuda_runtime.h>
#include <cuda_bf16.h>
#include <cstdint>
#include <math.h>

// Problem dims (fixed)
#define B_   4
#define L_   2048
#define D_   2048
#define R_   (B_*L_)        // 8192 rows
#define WN_  4
#define WELEM (D_*D_)       // 4194304
#define NCHUNK 64
#define CHUNK  32           // L_/NCHUNK

// ---------------- scratch (static device allocations; no cudaMalloc) ------
__device__ __align__(16) __nv_bfloat16 g_WQ[WN_*WELEM]; // ternary weights (32MB)
__device__ __align__(16) __nv_bfloat16 g_XQ[R_*D_];     // quantized acts  (32MB)
__device__ float g_GOUT[(size_t)R_*3*D_];        // raw int sums i|f|g      (192MB)
__device__ float g_SA[R_*D_];                    // h*sigmoid(h)            (64MB)
__device__ float g_cF[B_*NCHUNK*D_];
__device__ float g_cH[B_*NCHUNK*D_];
__device__ float g_carry[B_*NCHUNK*D_];
__device__ float g_xs[R_];                       // per-row act dequant scale
__device__ float g_os[R_];                       // per-row o dequant scale
__device__ float g_wpart[WN_*256];
__device__ float g_wmean[WN_];                   // clip(mean|W|,1e-5) == 1/ws

// ---------------- helpers ----------------
__device__ __forceinline__ float sigmoidf_(float x) { return 1.0f / (1.0f + expf(-x)); }
__device__ __forceinline__ float rsqrt_acc(float v) {
    float r = rsqrtf(v);
    r = r * (1.5f - 0.5f * v * r * r);
    return r;
}
__device__ __forceinline__ uint32_t smem_u32(const void* p) {
    uint32_t a;
    asm("{ .reg .u64 t; cvta.to.shared.u64 t, %1; cvt.u32.u64 %0, t; }" : "=r"(a) : "l"(p));
    return a;
}
// Deterministic block reductions (256 threads): shuffle within warp, smem
// broadcast of 8 warp partials, identical final value in every thread.
__device__ __forceinline__ float blk_sum(float v, float* red8, int tid) {
    #pragma unroll
    for (int o = 16; o > 0; o >>= 1) v += __shfl_xor_sync(0xFFFFFFFFu, v, o);
    if ((tid & 31) == 0) red8[tid >> 5] = v;
    __syncthreads();
    float s = 0.f;
    #pragma unroll
    for (int w = 0; w < 8; w++) s += red8[w];
    __syncthreads();
    return s;
}
__device__ __forceinline__ float blk_max(float v, float* red8, int tid) {
    #pragma unroll
    for (int o = 16; o > 0; o >>= 1) v = fmaxf(v, __shfl_xor_sync(0xFFFFFFFFu, v, o));
    if ((tid & 31) == 0) red8[tid >> 5] = v;
    __syncthreads();
    float s = red8[0];
    #pragma unroll
    for (int w = 1; w < 8; w++) s = fmaxf(s, red8[w]);
    __syncthreads();
    return s;
}

// ---------------- weight abs-mean: deterministic two-stage reduction -------
// float4-vectorized: 16 vector loads per thread (was 64 scalar).
__global__ void k_wabs_partial(const float* __restrict__ W0, const float* __restrict__ W1,
                               const float* __restrict__ W2, const float* __restrict__ W3) {
    const float* W = (blockIdx.y == 0) ? W0 : (blockIdx.y == 1) ? W1 : (blockIdx.y == 2) ? W2 : W3;
    int tid = threadIdx.x;
    const float4* W4 = (const float4*)W + (size_t)blockIdx.x * 4096 + tid;
    float s = 0.f;
    #pragma unroll 4
    for (int j = 0; j < 16; j++) {
        float4 v = W4[(size_t)j * 256];
        s += fabsf(v.x) + fabsf(v.y) + fabsf(v.z) + fabsf(v.w);
    }
    __shared__ float red8[8];
    s = blk_sum(s, red8, tid);
    if (tid == 0) g_wpart[blockIdx.y * 256 + blockIdx.x] = s;
}

__global__ void k_wfinal() {
    int w = blockIdx.x, tid = threadIdx.x;
    __shared__ float red8[8];
    float s = blk_sum(g_wpart[w * 256 + tid], red8, tid);
    if (tid == 0) {
        float m = s / (float)WELEM;
        g_wmean[w] = fmaxf(m, 1e-5f);
    }
}

// ---------------- ternary weight quantization -> bf16 ----------------------
__global__ void k_wquant(const float* __restrict__ W0, const float* __restrict__ W1,
                         const float* __restrict__ W2, const float* __restrict__ W3) {
    int i = blockIdx.x * blockDim.x + threadIdx.x;     // over WN_*WELEM/4
    int w = i >> 20;
    const float* W = (w == 0) ? W0 : (w == 1) ? W1 : (w == 2) ? W2 : W3;
    float4 v = ((const float4*)W)[i & 0xFFFFF];
    float ws = 1.0f / g_wmean[w];
    size_t o = (size_t)i * 4;
    g_WQ[o + 0] = __float2bfloat16(fminf(fmaxf(rintf(v.x * ws), -1.f), 1.f));
    g_WQ[o + 1] = __float2bfloat16(fminf(fmaxf(rintf(v.y * ws), -1.f), 1.f));
    g_WQ[o + 2] = __float2bfloat16(fminf(fmaxf(rintf(v.z * ws), -1.f), 1.f));
    g_WQ[o + 3] = __float2bfloat16(fminf(fmaxf(rintf(v.w * ws), -1.f), 1.f));
}

// ---------------- activation quantization (RMSNorm -> int8 grid, bf16) -----
// float4-vectorized loads (2 per thread) + 8B bf16x4 stores.
__global__ void k_actquant(const float* __restrict__ X) {
    int row = blockIdx.x, tid = threadIdx.x;
    const float4* xr4 = (const float4*)(X + (size_t)row * D_) + tid;
    __shared__ float red8[8];
    float4 va = xr4[0], vb = xr4[256];
    float ss = va.x * va.x + va.y * va.y + va.z * va.z + va.w * va.w
             + vb.x * vb.x + vb.y * vb.y + vb.z * vb.z + vb.w * vb.w;
    float tot = blk_sum(ss, red8, tid);
    float rms = rsqrt_acc(tot / (float)D_ + 1e-5f);
    float v[8] = {va.x, va.y, va.z, va.w, vb.x, vb.y, vb.z, vb.w};
    float ma = 0.f;
    #pragma unroll
    for (int j = 0; j < 8; j++) { v[j] *= rms; ma = fmaxf(ma, fabsf(v[j])); }
    float mx = fmaxf(blk_max(ma, red8, tid), 1e-5f);
    float s = 127.f / mx;
    __nv_bfloat16 q[8];
    #pragma unroll
    for (int j = 0; j < 8; j++)
        q[j] = __float2bfloat16(fminf(fmaxf(rintf(v[j] * s), -128.f), 127.f));
    __nv_bfloat16* xq = g_XQ + (size_t)row * D_;
    *(uint2*)(xq + tid * 4)        = *(uint2*)&q[0];
    *(uint2*)(xq + 1024 + tid * 4) = *(uint2*)&q[4];
    if (tid == 0) g_xs[row] = mx / 127.f;
}

// ---------------- bf16 HMMA GEMM: ldmatrix + cp.async, BK=64, 1 sync -------
// (R11-proven shape: CTA 128x128, warp 64x32, 2 CTAs/SM)
#define STAGES 3
#define ROWB   144                      // padded row stride (bytes): 128 + 16
#define TILEB  (128*ROWB)               // 18432
#define STGB   (2*TILEB)                // 36864
#define GSMEM  (STAGES*STGB)            // 110592

__device__ __forceinline__ void cp16(uint32_t dst, const void* src) {
    asm volatile("cp.async.cg.shared.global [%0], [%1], 16;" :: "r"(dst), "l"(src));
}
#define LDSM4(r0, r1, r2, r3, addr) \
    asm volatile("ldmatrix.sync.aligned.m8n8.x4.shared.b16 {%0,%1,%2,%3}, [%4];" \
        : "=r"(r0), "=r"(r1), "=r"(r2), "=r"(r3) : "r"(addr))

__global__ void __launch_bounds__(256, 2) k_gemm_bf16(
    const __nv_bfloat16* __restrict__ A, const __nv_bfloat16* __restrict__ Bm,
    float* __restrict__ C, int N,
    const float* __restrict__ rowscale, const float* __restrict__ wscale) {

    extern __shared__ char sm8[];
    uint32_t sb = smem_u32(sm8);
    const int K = D_;
    int tid = threadIdx.x, lane = tid & 31, warp = tid >> 5;
    int wm = (warp & 1) * 64, wn = (warp >> 1) * 32;
    int g = lane >> 2, t4 = lane & 3;
    int bm = blockIdx.y * 128, bn = blockIdx.x * 128;

    const __nv_bfloat16* Ab = A + (size_t)bm * K;
    const __nv_bfloat16* Bb = Bm + (size_t)bn * K;

    float acc[4][4][4];
    #pragma unroll
    for (int a = 0; a < 4; a++)
        #pragma unroll
        for (int b = 0; b < 4; b++)
            #pragma unroll
            for (int c = 0; c < 4; c++) acc[a][b][c] = 0.f;

    uint32_t aoff[4], boff[2];
    {
        int l = lane;
        int rlo = (l & 7) + ((l >> 3) & 1) * 8;
        int khalf = (l >> 4) * 16;
        #pragma unroll
        for (int mi = 0; mi < 4; mi++)
            aoff[mi] = (uint32_t)((wm + mi * 16 + rlo) * ROWB + khalf);
        int nrow = (l & 7) + (l >> 4) * 8;
        int bk = ((l >> 3) & 1) * 16;
        #pragma unroll
        for (int p = 0; p < 2; p++)
            boff[p] = (uint32_t)((wn + p * 16 + nrow) * ROWB + bk);
    }

    #pragma unroll
    for (int s = 0; s < STAGES - 1; s++) {
        #pragma unroll
        for (int i = 0; i < 8; i++) {
            int id = tid + i * 256;
            int tile = id >> 10;
            int c = id & 1023;
            int row = c >> 3, kc = c & 7;
            const __nv_bfloat16* src = (tile ? Bb : Ab) + (size_t)row * K + s * 64 + kc * 8;
            cp16(sb + s * STGB + tile * TILEB + row * ROWB + kc * 16, src);
        }
        asm volatile("cp.async.commit_group;");
    }

    for (int kt = 0; kt < 32; kt++) {
        asm volatile("cp.async.wait_group %0;" :: "n"(STAGES - 2));
        __syncthreads();

        int pf = kt + STAGES - 1;
        if (pf < 32) {
            int s = pf % STAGES;
            #pragma unroll
            for (int i = 0; i < 8; i++) {
                int id = tid + i * 256;
                int tile = id >> 10;
                int c = id & 1023;
                int row = c >> 3, kc = c & 7;
                const __nv_bfloat16* src = (tile ? Bb : Ab) + (size_t)row * K + pf * 64 + kc * 8;
                cp16(sb + s * STGB + tile * TILEB + row * ROWB + kc * 16, src);
            }
            asm volatile("cp.async.commit_group;");
        } else {
            asm volatile("cp.async.commit_group;");
        }

        uint32_t aB = sb + (kt % STAGES) * STGB;
        uint32_t bB = aB + TILEB;
        #pragma unroll
        for (int kk = 0; kk < 4; kk++) {
            uint32_t af[4][4], bf[4][2];
            #pragma unroll
            for (int mi = 0; mi < 4; mi++)
                LDSM4(af[mi][0], af[mi][1], af[mi][2], af[mi][3],
                      aB + aoff[mi] + kk * 32);
            #pragma unroll
            for (int p = 0; p < 2; p++)
                LDSM4(bf[2 * p][0], bf[2 * p][1], bf[2 * p + 1][0], bf[2 * p + 1][1],
                      bB + boff[p] + kk * 32);
            #pragma unroll
            for (int mi = 0; mi < 4; mi++)
                #pragma unroll
                for (int ni = 0; ni < 4; ni++) {
                    asm volatile(
                        "mma.sync.aligned.m16n8k16.row.col.f32.bf16.bf16.f32 "
                        "{%0,%1,%2,%3}, {%4,%5,%6,%7}, {%8,%9}, {%0,%1,%2,%3};\n"
                        : "+f"(acc[mi][ni][0]), "+f"(acc[mi][ni][1]),
                          "+f"(acc[mi][ni][2]), "+f"(acc[mi][ni][3])
                        : "r"(af[mi][0]), "r"(af[mi][1]), "r"(af[mi][2]), "r"(af[mi][3]),
                          "r"(bf[ni][0]), "r"(bf[ni][1]));
                }
        }
    }

    float wsc = rowscale ? (*wscale) : 1.f;
    #pragma unroll
    for (int mi = 0; mi < 4; mi++) {
        int r0 = bm + wm + mi * 16 + g;
        int r1 = r0 + 8;
        float s0 = rowscale ? rowscale[r0] * wsc : 1.f;
        float s1 = rowscale ? rowscale[r1] * wsc : 1.f;
        #pragma unroll
        for (int ni = 0; ni < 4; ni++) {
            int col = bn + wn + ni * 8 + t4 * 2;
            float2 v0, v1;
            v0.x = acc[mi][ni][0] * s0;
            v0.y = acc[mi][ni][1] * s0;
            v1.x = acc[mi][ni][2] * s1;
            v1.y = acc[mi][ni][3] * s1;
            *(float2*)&C[(size_t)r0 * N + col] = v0;
            *(float2*)&C[(size_t)r1 * N + col] = v1;
        }
    }
}

// ---------------- HGRN scan (3-pass chunked, i/f recomputed from GOUT) -----
__global__ void k_scan1() {
    int idx = blockIdx.x * 256 + threadIdx.x;   // B_*NCHUNK*D_ = 524288
    int d = idx & 2047, c = (idx >> 11) & (NCHUNK - 1), b = idx >> 17;
    int row0 = b * L_ + c * CHUNK;
    float w0 = g_wmean[0], w1 = g_wmean[1];
    float F = 1.f, H = 0.f;
    for (int t = 0; t < CHUNK; t++) {
        int row = row0 + t;
        float sx = g_xs[row];
        float iv = g_GOUT[(size_t)row * 6144 + d       ] * (sx * w0);
        float fv = g_GOUT[(size_t)row * 6144 + 2048 + d] * (sx * w1);
        float f = sigmoidf_(fv);
        float i = iv * sigmoidf_(iv) * (1.f - f);
        H = f * H + i;
        F *= f;
    }
    int o = (b * NCHUNK + c) * D_ + d;
    g_cF[o] = F; g_cH[o] = H;
}

__global__ void k_scan2() {
    int idx = blockIdx.x * 256 + threadIdx.x;   // B_*D_ = 8192
    int d = idx & 2047, b = idx >> 11;
    float carry = 0.f;
    for (int c = 0; c < NCHUNK; c++) {
        int o = (b * NCHUNK + c) * D_ + d;
        g_carry[o] = carry;
        carry = g_cF[o] * carry + g_cH[o];
    }
}

__global__ void k_scan3() {
    int idx = blockIdx.x * 256 + threadIdx.x;   // B_*NCHUNK*D_
    int d = idx & 2047, c = (idx >> 11) & (NCHUNK - 1), b = idx >> 17;
    int row0 = b * L_ + c * CHUNK;
    float w0 = g_wmean[0], w1 = g_wmean[1];
    float h = g_carry[(b * NCHUNK + c) * D_ + d];
    for (int t = 0; t < CHUNK; t++) {
        int row = row0 + t;
        float sx = g_xs[row];
        float iv = g_GOUT[(size_t)row * 6144 + d       ] * (sx * w0);
        float fv = g_GOUT[(size_t)row * 6144 + 2048 + d] * (sx * w1);
        float f = sigmoidf_(fv);
        float i = iv * sigmoidf_(iv) * (1.f - f);
        h = f * h + i;
        g_SA[(size_t)row * D_ + d] = h * sigmoidf_(h);
    }
}

// ---------------- o = rmsnorm(g)*w*(h*sig(h)), then re-quantize o ----------
__global__ void k_og(const float* __restrict__ gnw) {
    int row = blockIdx.x, tid = threadIdx.x;
    __shared__ float red8[8];
    float sg = g_xs[row] * g_wmean[2];
    float gv[8]; float ss = 0.f;
    #pragma unroll
    for (int j = 0; j < 8; j++) {
        gv[j] = g_GOUT[(size_t)row * 6144 + 4096 + tid + j * 256] * sg;
        ss += gv[j] * gv[j];
    }
    float tot = blk_sum(ss, red8, tid);
    float rg = rsqrt_acc(tot / (float)D_ + 1e-5f);

    float ov[8]; ss = 0.f;
    #pragma unroll
    for (int j = 0; j < 8; j++) {
        float hs = g_SA[(size_t)row * D_ + tid + j * 256];
        ov[j] = gv[j] * rg * gnw[tid + j * 256] * hs;
        ss += ov[j] * ov[j];
    }
    float tot2 = blk_sum(ss, red8, tid);
    float ro = rsqrt_acc(tot2 / (float)D_ + 1e-5f);

    float ma = 0.f;
    #pragma unroll
    for (int j = 0; j < 8; j++) { ov[j] *= ro; ma = fmaxf(ma, fabsf(ov[j])); }
    float mx = fmaxf(blk_max(ma, red8, tid), 1e-5f);
    float s = 127.f / mx;
    #pragma unroll
    for (int j = 0; j < 8; j++) {
        float q = fminf(fmaxf(rintf(ov[j] * s), -128.f), 127.f);
        g_XQ[(size_t)row * D_ + tid + j * 256] = __float2bfloat16(q);
    }
    if (tid == 0) g_os[row] = mx / 127.f;
}

// ---------------- launch ---------------------------------------------------
extern "C" void kernel_launch(void* const* d_in, const int* in_sizes, int n_in,
                              void* d_out, int out_size) {
    const float* X   = (const float*)d_in[0];
    const float* Wi  = (const float*)d_in[1];
    const float* Wf  = (const float*)d_in[2];
    const float* Wg  = (const float*)d_in[3];
    const float* Wo  = (const float*)d_in[4];
    const float* gnw = (const float*)d_in[5];
    float* out = (float*)d_out;

    void *pWQ = nullptr, *pXQ = nullptr, *pGOUT = nullptr, *pOS = nullptr, *pWM = nullptr;
    cudaGetSymbolAddress(&pWQ, g_WQ);
    cudaGetSymbolAddress(&pXQ, g_XQ);
    cudaGetSymbolAddress(&pGOUT, g_GOUT);
    cudaGetSymbolAddress(&pOS, g_os);
    cudaGetSymbolAddress(&pWM, g_wmean);

    cudaFuncSetAttribute(k_gemm_bf16, cudaFuncAttributeMaxDynamicSharedMemorySize, GSMEM);

    // 1. weight scales (deterministic)
    k_wabs_partial<<<dim3(256, 4), 256>>>(Wi, Wf, Wg, Wo);
    k_wfinal<<<4, 256>>>();
    // 2. quantize weights (ternary bf16)
    k_wquant<<<16384, 256>>>(Wi, Wf, Wg, Wo);
    // 3. quantize activations (bf16 int grid)
    k_actquant<<<R_, 256>>>(X);
    // 4. fused HMMA GEMM for i|f|g raw integer sums: [8192 x 6144 x 2048]
    k_gemm_bf16<<<dim3(6144 / 128, R_ / 128), 256, GSMEM>>>(
        (const __nv_bfloat16*)pXQ, (const __nv_bfloat16*)pWQ, (float*)pGOUT,
        3 * D_, nullptr, nullptr);
    // 5. HGRN scan (64 chunks of 32; i/f recomputed from GOUT, no staging)
    k_scan1<<<(B_ * NCHUNK * D_) / 256, 256>>>();
    k_scan2<<<(B_ * D_) / 256, 256>>>();
    k_scan3<<<(B_ * NCHUNK * D_) / 256, 256>>>();
    // 6. output gate + o quantization
    k_og<<<R_, 256>>>(gnw);
    // 7. final HMMA GEMM with dequant epilogue -> d_out
    k_gemm_bf16<<<dim3(D_ / 128, R_ / 128), 256, GSMEM>>>(
        (const __nv_bfloat16*)pXQ, (const __nv_bfloat16*)pWQ + (size_t)3 * WELEM, out,
        D_, (const float*)pOS, (const float*)pWM + 3);
}